// round 15
// baseline (speedup 1.0000x reference)
#include <cuda_runtime.h>

#define NCLASS 128
#define NTHR   256
#define OCC    4
#define NBLK   (152 * OCC)   // 608 blocks: single wave, 32 warps/SM, persistent
#define UNROLL 8
#define WPB    (NTHR / 32)   // warps per block

// Global scratch — zero-initialized at module load; finalize re-zeros after
// consuming so every graph replay starts from a clean state.
__device__ float        g_colsum[NCLASS];
__device__ unsigned int g_counts[NCLASS];
__device__ float        g_picked;

// One warp per row. Lane l owns columns [4l, 4l+3] via one float4 load.
// Batched v[8] loads -> 8 LDG.128 in flight per thread (measured-fastest
// body). Single-wave grid. __ldcs only on the 512MB pred stream.
// PDL: trigger programmatic launch completion at the TOP of the kernel —
// the finalize kernel stages/launches immediately and parks in
// cudaGridDependencySynchronize(); memory ordering comes solely from that
// sync, so an early trigger is safe (documented PDL pattern).
__global__ __launch_bounds__(NTHR, OCC) void loss_main_kernel(
    const float* __restrict__ pred,
    const int*   __restrict__ tgt,
    int n)
{
    __shared__ float        s_colsum[NCLASS];
    __shared__ unsigned int s_counts[NCLASS];
    __shared__ float        s_picked;

    const int tid  = threadIdx.x;
    const int lane = tid & 31;
    const int wrp  = tid >> 5;

    if (tid < NCLASS) { s_colsum[tid] = 0.0f; s_counts[tid] = 0u; }
    if (tid == 0) s_picked = 0.0f;
    __syncthreads();

    // Early trigger: let the dependent finalize grid launch and park now,
    // hiding its entire staging latency under our ~85us main loop.
    cudaTriggerProgrammaticLaunchCompletion();

    const int gwarp = blockIdx.x * WPB + wrp;
    const int W     = NBLK * WPB;            // total warps (stride)

    float a0 = 0.f, a1 = 0.f, a2 = 0.f, a3 = 0.f;
    float pick = 0.f;

    int r = gwarp;
    for (; r + (UNROLL - 1) * W < n; r += UNROLL * W) {
        float4 v[UNROLL];
        int    t[UNROLL];
        #pragma unroll
        for (int j = 0; j < UNROLL; j++) {
            const int rj = r + j * W;
            v[j] = __ldcs(reinterpret_cast<const float4*>(
                       pred + (size_t)rj * NCLASS + lane * 4));
            t[j] = tgt[rj];
        }
        #pragma unroll
        for (int j = 0; j < UNROLL; j++) {
            a0 += __expf(v[j].x); a1 += __expf(v[j].y);
            a2 += __expf(v[j].z); a3 += __expf(v[j].w);
            if ((t[j] >> 2) == lane) {
                const int k = t[j] & 3;
                pick += (k == 0) ? v[j].x : (k == 1) ? v[j].y
                      : (k == 2) ? v[j].z : v[j].w;
            }
            if (lane == j) atomicAdd(&s_counts[t[j]], 1u);  // lane j handles row j
        }
    }
    // Tail
    for (; r < n; r += W) {
        const float4 v = __ldcs(reinterpret_cast<const float4*>(
                             pred + (size_t)r * NCLASS + lane * 4));
        const int t = tgt[r];
        a0 += __expf(v.x); a1 += __expf(v.y); a2 += __expf(v.z); a3 += __expf(v.w);
        if ((t >> 2) == lane) {
            const int k = t & 3;
            pick += (k == 0) ? v.x : (k == 1) ? v.y : (k == 2) ? v.z : v.w;
        }
        if (lane == 0) atomicAdd(&s_counts[t], 1u);
    }

    // Warp-reduce picked sum.
    #pragma unroll
    for (int off = 16; off > 0; off >>= 1)
        pick += __shfl_xor_sync(0xFFFFFFFFu, pick, off);
    if (lane == 0) atomicAdd(&s_picked, pick);

    // Per-lane column partials -> shared (cross-warp combine).
    atomicAdd(&s_colsum[lane * 4 + 0], a0);
    atomicAdd(&s_colsum[lane * 4 + 1], a1);
    atomicAdd(&s_colsum[lane * 4 + 2], a2);
    atomicAdd(&s_colsum[lane * 4 + 3], a3);
    __syncthreads();

    // Flush block partials to global; visibility to finalize is guaranteed
    // by its cudaGridDependencySynchronize() (waits for full-grid completion).
    if (tid < NCLASS) {
        atomicAdd(&g_colsum[tid], s_colsum[tid]);
        if (s_counts[tid]) atomicAdd(&g_counts[tid], s_counts[tid]);
    }
    if (tid == 0) atomicAdd(&g_picked, s_picked);
}

__global__ void finalize_kernel(float* __restrict__ out, int n) {
    // Park until ALL of the primary grid's memory operations are visible.
    cudaGridDependencySynchronize();

    __shared__ float s_part[4];
    const int tid  = threadIdx.x;   // 128 threads
    const int lane = tid & 31;
    const int wrp  = tid >> 5;

    float diff = fabsf((float)g_counts[tid] - g_colsum[tid]);
    const float picked = g_picked;

    // Re-zero scratch for the next graph replay (after reads above).
    g_colsum[tid] = 0.0f;
    g_counts[tid] = 0u;
    if (tid == 0) g_picked = 0.0f;

    #pragma unroll
    for (int off = 16; off > 0; off >>= 1)
        diff += __shfl_xor_sync(0xFFFFFFFFu, diff, off);
    if (lane == 0) s_part[wrp] = diff;
    __syncthreads();
    if (tid == 0) {
        const float extra = (s_part[0] + s_part[1] + s_part[2] + s_part[3]) / (float)n;
        out[0] = -picked / (float)n + extra;
    }
}

extern "C" void kernel_launch(void* const* d_in, const int* in_sizes, int n_in,
                              void* d_out, int out_size) {
    const float* pred = (const float*)d_in[0];
    const int*   tgt  = (const int*)d_in[1];
    float*       out  = (float*)d_out;
    const int n = in_sizes[1];  // number of rows / targets

    loss_main_kernel<<<NBLK, NTHR>>>(pred, tgt, n);

    // Finalize with Programmatic Stream Serialization: launches as soon as
    // the primary triggers (top of kernel); parks in grid-dependency sync.
    cudaLaunchConfig_t cfg = {};
    cfg.gridDim  = dim3(1, 1, 1);
    cfg.blockDim = dim3(NCLASS, 1, 1);
    cfg.dynamicSmemBytes = 0;
    cfg.stream = 0;
    cudaLaunchAttribute attrs[1];
    attrs[0].id = cudaLaunchAttributeProgrammaticStreamSerialization;
    attrs[0].val.programmaticStreamSerializationAllowed = 1;
    cfg.attrs = attrs;
    cfg.numAttrs = 1;
    cudaLaunchKernelEx(&cfg, finalize_kernel, out, n);
}

// round 16
// speedup vs baseline: 1.0022x; 1.0022x over previous
#include <cuda_runtime.h>

#define NCLASS 128
#define NTHR   256
#define OCC    4
#define NBLK   (152 * OCC)   // 608 blocks: single wave, 32 warps/SM, persistent
#define UNROLL 8
#define WPB    (NTHR / 32)   // warps per block

// Global scratch — zero-initialized at module load; finalize re-zeros after
// consuming so every graph replay starts from a clean state.
__device__ float        g_colsum[NCLASS];
__device__ unsigned int g_counts[NCLASS];
__device__ float        g_picked;

// One warp per row. Lane l owns columns [4l, 4l+3] via one float4 load.
// Batched v[8] loads -> 8 LDG.128 in flight per thread (measured-fastest
// body across 7 config variants; ~6.4 TB/s effective, chip ceiling for this
// pattern). Single-wave grid: blocks persist for the whole kernel so the LDG
// pipeline fills once per SM. __ldcs on the 512MB pred stream only; targets
// use default caching (one L1 sector serves the block's consecutive rows).
// PDL: trigger right after the main loop — finalize stages under the block
// epilogues; memory ordering comes from cudaGridDependencySynchronize().
__global__ __launch_bounds__(NTHR, OCC) void loss_main_kernel(
    const float* __restrict__ pred,
    const int*   __restrict__ tgt,
    int n)
{
    __shared__ float        s_colsum[NCLASS];
    __shared__ unsigned int s_counts[NCLASS];
    __shared__ float        s_picked;

    const int tid  = threadIdx.x;
    const int lane = tid & 31;
    const int wrp  = tid >> 5;

    if (tid < NCLASS) { s_colsum[tid] = 0.0f; s_counts[tid] = 0u; }
    if (tid == 0) s_picked = 0.0f;
    __syncthreads();

    const int gwarp = blockIdx.x * WPB + wrp;
    const int W     = NBLK * WPB;            // total warps (stride)

    float a0 = 0.f, a1 = 0.f, a2 = 0.f, a3 = 0.f;
    float pick = 0.f;

    int r = gwarp;
    for (; r + (UNROLL - 1) * W < n; r += UNROLL * W) {
        float4 v[UNROLL];
        int    t[UNROLL];
        #pragma unroll
        for (int j = 0; j < UNROLL; j++) {
            const int rj = r + j * W;
            v[j] = __ldcs(reinterpret_cast<const float4*>(
                       pred + (size_t)rj * NCLASS + lane * 4));
            t[j] = tgt[rj];
        }
        #pragma unroll
        for (int j = 0; j < UNROLL; j++) {
            a0 += __expf(v[j].x); a1 += __expf(v[j].y);
            a2 += __expf(v[j].z); a3 += __expf(v[j].w);
            if ((t[j] >> 2) == lane) {
                const int k = t[j] & 3;
                pick += (k == 0) ? v[j].x : (k == 1) ? v[j].y
                      : (k == 2) ? v[j].z : v[j].w;
            }
            if (lane == j) atomicAdd(&s_counts[t[j]], 1u);  // lane j handles row j
        }
    }
    // Tail
    for (; r < n; r += W) {
        const float4 v = __ldcs(reinterpret_cast<const float4*>(
                             pred + (size_t)r * NCLASS + lane * 4));
        const int t = tgt[r];
        a0 += __expf(v.x); a1 += __expf(v.y); a2 += __expf(v.z); a3 += __expf(v.w);
        if ((t >> 2) == lane) {
            const int k = t & 3;
            pick += (k == 0) ? v.x : (k == 1) ? v.y : (k == 2) ? v.z : v.w;
        }
        if (lane == 0) atomicAdd(&s_counts[t], 1u);
    }

    // Main loop done: let the dependent finalize grid stage/launch while the
    // blocks run their reduction epilogues.
    cudaTriggerProgrammaticLaunchCompletion();

    // Warp-reduce picked sum.
    #pragma unroll
    for (int off = 16; off > 0; off >>= 1)
        pick += __shfl_xor_sync(0xFFFFFFFFu, pick, off);
    if (lane == 0) atomicAdd(&s_picked, pick);

    // Per-lane column partials -> shared (cross-warp combine).
    atomicAdd(&s_colsum[lane * 4 + 0], a0);
    atomicAdd(&s_colsum[lane * 4 + 1], a1);
    atomicAdd(&s_colsum[lane * 4 + 2], a2);
    atomicAdd(&s_colsum[lane * 4 + 3], a3);
    __syncthreads();

    // Flush block partials to global; visibility to finalize is guaranteed
    // by its cudaGridDependencySynchronize() (waits for full-grid completion).
    if (tid < NCLASS) {
        atomicAdd(&g_colsum[tid], s_colsum[tid]);
        if (s_counts[tid]) atomicAdd(&g_counts[tid], s_counts[tid]);
    }
    if (tid == 0) atomicAdd(&g_picked, s_picked);
}

__global__ void finalize_kernel(float* __restrict__ out, int n) {
    // Park until ALL of the primary grid's memory operations are visible.
    cudaGridDependencySynchronize();

    __shared__ float s_part[4];
    const int tid  = threadIdx.x;   // 128 threads
    const int lane = tid & 31;
    const int wrp  = tid >> 5;

    float diff = fabsf((float)g_counts[tid] - g_colsum[tid]);
    const float picked = g_picked;

    // Re-zero scratch for the next graph replay (after reads above).
    g_colsum[tid] = 0.0f;
    g_counts[tid] = 0u;
    if (tid == 0) g_picked = 0.0f;

    #pragma unroll
    for (int off = 16; off > 0; off >>= 1)
        diff += __shfl_xor_sync(0xFFFFFFFFu, diff, off);
    if (lane == 0) s_part[wrp] = diff;
    __syncthreads();
    if (tid == 0) {
        const float extra = (s_part[0] + s_part[1] + s_part[2] + s_part[3]) / (float)n;
        out[0] = -picked / (float)n + extra;
    }
}

extern "C" void kernel_launch(void* const* d_in, const int* in_sizes, int n_in,
                              void* d_out, int out_size) {
    const float* pred = (const float*)d_in[0];
    const int*   tgt  = (const int*)d_in[1];
    float*       out  = (float*)d_out;
    const int n = in_sizes[1];  // number of rows / targets

    loss_main_kernel<<<NBLK, NTHR>>>(pred, tgt, n);

    // Finalize with Programmatic Stream Serialization: launches as soon as
    // the primary triggers; parks in grid-dependency sync for ordering.
    cudaLaunchConfig_t cfg = {};
    cfg.gridDim  = dim3(1, 1, 1);
    cfg.blockDim = dim3(NCLASS, 1, 1);
    cfg.dynamicSmemBytes = 0;
    cfg.stream = 0;
    cudaLaunchAttribute attrs[1];
    attrs[0].id = cudaLaunchAttributeProgrammaticStreamSerialization;
    attrs[0].val.programmaticStreamSerializationAllowed = 1;
    cfg.attrs = attrs;
    cfg.numAttrs = 1;
    cudaLaunchKernelEx(&cfg, finalize_kernel, out, n);
}

// round 17
// speedup vs baseline: 1.0026x; 1.0004x over previous
#include <cuda_runtime.h>

#define NCLASS 128
#define NTHR   256
#define OCC    4
#define NBLK   (152 * OCC)   // 608 blocks: single wave, 32 warps/SM, persistent
#define UNROLL 8
#define WPB    (NTHR / 32)   // warps per block

// Global scratch — zero-initialized at module load; finalize re-zeros after
// consuming so every graph replay starts from a clean state.
__device__ float        g_colsum[NCLASS];
__device__ unsigned int g_counts[NCLASS];
__device__ float        g_picked;

// FINAL (converged) kernel.
// One warp per row. Lane l owns columns [4l, 4l+3] via one float4 load.
// Batched v[8] loads -> 8 LDG.128 in flight per thread (measured-fastest
// body across 7 config variants; ~6.4 TB/s effective = chip ceiling for this
// pattern). Single-wave grid: blocks persist for the whole kernel so the LDG
// pipeline fills once per SM. __ldcs on the 512MB pred stream only; targets
// use default caching (one L1 sector serves the block's consecutive rows).
// PDL: trigger after the main loop — finalize stages under the block
// epilogues; memory ordering comes from cudaGridDependencySynchronize().
__global__ __launch_bounds__(NTHR, OCC) void loss_main_kernel(
    const float* __restrict__ pred,
    const int*   __restrict__ tgt,
    int n)
{
    __shared__ float        s_colsum[NCLASS];
    __shared__ unsigned int s_counts[NCLASS];
    __shared__ float        s_picked;

    const int tid  = threadIdx.x;
    const int lane = tid & 31;
    const int wrp  = tid >> 5;

    if (tid < NCLASS) { s_colsum[tid] = 0.0f; s_counts[tid] = 0u; }
    if (tid == 0) s_picked = 0.0f;
    __syncthreads();

    const int gwarp = blockIdx.x * WPB + wrp;
    const int W     = NBLK * WPB;            // total warps (stride)

    float a0 = 0.f, a1 = 0.f, a2 = 0.f, a3 = 0.f;
    float pick = 0.f;

    int r = gwarp;
    for (; r + (UNROLL - 1) * W < n; r += UNROLL * W) {
        float4 v[UNROLL];
        int    t[UNROLL];
        #pragma unroll
        for (int j = 0; j < UNROLL; j++) {
            const int rj = r + j * W;
            v[j] = __ldcs(reinterpret_cast<const float4*>(
                       pred + (size_t)rj * NCLASS + lane * 4));
            t[j] = tgt[rj];
        }
        #pragma unroll
        for (int j = 0; j < UNROLL; j++) {
            a0 += __expf(v[j].x); a1 += __expf(v[j].y);
            a2 += __expf(v[j].z); a3 += __expf(v[j].w);
            if ((t[j] >> 2) == lane) {
                const int k = t[j] & 3;
                pick += (k == 0) ? v[j].x : (k == 1) ? v[j].y
                      : (k == 2) ? v[j].z : v[j].w;
            }
            if (lane == j) atomicAdd(&s_counts[t[j]], 1u);  // lane j handles row j
        }
    }
    // Tail
    for (; r < n; r += W) {
        const float4 v = __ldcs(reinterpret_cast<const float4*>(
                             pred + (size_t)r * NCLASS + lane * 4));
        const int t = tgt[r];
        a0 += __expf(v.x); a1 += __expf(v.y); a2 += __expf(v.z); a3 += __expf(v.w);
        if ((t >> 2) == lane) {
            const int k = t & 3;
            pick += (k == 0) ? v.x : (k == 1) ? v.y : (k == 2) ? v.z : v.w;
        }
        if (lane == 0) atomicAdd(&s_counts[t], 1u);
    }

    // Main loop done: let the dependent finalize grid stage/launch while the
    // blocks run their reduction epilogues.
    cudaTriggerProgrammaticLaunchCompletion();

    // Warp-reduce picked sum.
    #pragma unroll
    for (int off = 16; off > 0; off >>= 1)
        pick += __shfl_xor_sync(0xFFFFFFFFu, pick, off);
    if (lane == 0) atomicAdd(&s_picked, pick);

    // Per-lane column partials -> shared (cross-warp combine).
    atomicAdd(&s_colsum[lane * 4 + 0], a0);
    atomicAdd(&s_colsum[lane * 4 + 1], a1);
    atomicAdd(&s_colsum[lane * 4 + 2], a2);
    atomicAdd(&s_colsum[lane * 4 + 3], a3);
    __syncthreads();

    // Flush block partials to global; visibility to finalize is guaranteed
    // by its cudaGridDependencySynchronize() (waits for full-grid completion).
    if (tid < NCLASS) {
        atomicAdd(&g_colsum[tid], s_colsum[tid]);
        if (s_counts[tid]) atomicAdd(&g_counts[tid], s_counts[tid]);
    }
    if (tid == 0) atomicAdd(&g_picked, s_picked);
}

__global__ void finalize_kernel(float* __restrict__ out, int n) {
    // Park until ALL of the primary grid's memory operations are visible.
    cudaGridDependencySynchronize();

    __shared__ float s_part[4];
    const int tid  = threadIdx.x;   // 128 threads
    const int lane = tid & 31;
    const int wrp  = tid >> 5;

    float diff = fabsf((float)g_counts[tid] - g_colsum[tid]);
    const float picked = g_picked;

    // Re-zero scratch for the next graph replay (after reads above).
    g_colsum[tid] = 0.0f;
    g_counts[tid] = 0u;
    if (tid == 0) g_picked = 0.0f;

    #pragma unroll
    for (int off = 16; off > 0; off >>= 1)
        diff += __shfl_xor_sync(0xFFFFFFFFu, diff, off);
    if (lane == 0) s_part[wrp] = diff;
    __syncthreads();
    if (tid == 0) {
        const float extra = (s_part[0] + s_part[1] + s_part[2] + s_part[3]) / (float)n;
        out[0] = -picked / (float)n + extra;
    }
}

extern "C" void kernel_launch(void* const* d_in, const int* in_sizes, int n_in,
                              void* d_out, int out_size) {
    const float* pred = (const float*)d_in[0];
    const int*   tgt  = (const int*)d_in[1];
    float*       out  = (float*)d_out;
    const int n = in_sizes[1];  // number of rows / targets

    loss_main_kernel<<<NBLK, NTHR>>>(pred, tgt, n);

    // Finalize with Programmatic Stream Serialization: launches as soon as
    // the primary triggers; parks in grid-dependency sync for ordering.
    cudaLaunchConfig_t cfg = {};
    cfg.gridDim  = dim3(1, 1, 1);
    cfg.blockDim = dim3(NCLASS, 1, 1);
    cfg.dynamicSmemBytes = 0;
    cfg.stream = 0;
    cudaLaunchAttribute attrs[1];
    attrs[0].id = cudaLaunchAttributeProgrammaticStreamSerialization;
    attrs[0].val.programmaticStreamSerializationAllowed = 1;
    cfg.attrs = attrs;
    cfg.numAttrs = 1;
    cudaLaunchKernelEx(&cfg, finalize_kernel, out, n);
}